// round 16
// baseline (speedup 1.0000x reference)
#include <cuda_runtime.h>
#include <cuda_fp16.h>
#include <math.h>

// Problem constants (fixed shapes)
constexpr int NX = 128, NY = 128, NZ = 128;
constexpr int NA = 96, NU = 128, NV = 128, NSTEPS = 128;
constexpr int NZQ = NZ / 4;                 // 32 z-quads
constexpr int ACHUNKS = 4;                  // 96 angles / 24 per block
constexpr int A_PER_BLOCK = NA / ACHUNKS;   // 24
constexpr int THREADS = 1024;
constexpr int J_ITERS = 3;                  // 8 angle slots x 3 = 24 angles

// Zero-padded shared tile (cell = 2x half2 = 4 z-slices, 8B). Linear layout.
// EXACT clipping keeps coords in [OFS-1-eps, OFS+128+eps]; with OFS=2 all
// touched indices (incl. +1 corners) lie in [0, 131].
constexpr int OFS      = 2;
constexpr int SM_ROWS  = 132;
constexpr int PITCH    = 133;               // odd pitch
constexpr int SM_ELEMS = SM_ROWS * PITCH;   // 17556 cells = 140448 B

// T = 0.5*sqrt(127^2 + 127^2), delta_t = 2T/128 (double -> f32)
constexpr float TF  = (float)89.80256121069154;
constexpr float DTF = (float)1.4031650189170553;
constexpr float T0F = -TF + 0.5f * DTF;

struct h2x2 { __half2 a, b; };   // 4 z values (z0,z1 | z2,z3)

// 4 MB scratch: vol as [z-quad][y][x], fp16, x contiguous
__device__ h2x2 g_vol4[NZQ * NY * NX];

// ---------------------------------------------------------------------------
// Transpose vol[(x*NY + y)*NZ + z] -> g_vol4[(zq*NY + y)*NX + x] (4 z packed)
// ---------------------------------------------------------------------------
__global__ void transpose_kernel(const float* __restrict__ vol) {
    __shared__ float tile[32][33];           // [x local][z local]
    const int y  = blockIdx.z;
    const int x0 = blockIdx.x * 32;
    const int z0 = blockIdx.y * 32;
    const int tx = threadIdx.x;      // 0..31
    const int ty = threadIdx.y;      // 0..7

#pragma unroll
    for (int j = 0; j < 32; j += 8) {
        int x = x0 + ty + j;
        int z = z0 + tx;
        tile[ty + j][tx] = vol[(x * NY + y) * NZ + z];   // coalesced in z
    }
    __syncthreads();
    {
        int zql = ty;                        // 0..7 (z-quad within 32-z tile)
        int x   = x0 + tx;
        int zq  = (z0 >> 2) + zql;
        h2x2 v;
        v.a = __floats2half2_rn(tile[tx][4 * zql + 0], tile[tx][4 * zql + 1]);
        v.b = __floats2half2_rn(tile[tx][4 * zql + 2], tile[tx][4 * zql + 3]);
        g_vol4[(zq * NY + y) * NX + x] = v;  // coalesced 8B
    }
}

// ---------------------------------------------------------------------------
// EXACT step range for val(i) = A + i*d in (lo_b, hi_b): lo = ceil, hi = floor.
// Steps excluded at the boundary have (near-)zero bilinear weight into the
// zero border; fp rounding of the bound (~1e-4 px) changes results by <1e-8.
// ---------------------------------------------------------------------------
__device__ __forceinline__ void slab_range(float A, float d, float lo_b, float hi_b,
                                           int& lo, int& hi) {
    if (fabsf(d) < 1e-8f) {
        if (A > lo_b && A < hi_b) { lo = 0; hi = NSTEPS - 1; }
        else                      { lo = 1; hi = 0; }
        return;
    }
    float inv = 1.0f / d;
    float i1 = (lo_b - A) * inv;
    float i2 = (hi_b - A) * inv;
    float flo = fmaxf(fminf(i1, i2), -1e9f);
    float fhi = fminf(fmaxf(i1, i2),  1e9f);
    lo = max(0, __float2int_ru(flo));
    hi = min(NSTEPS - 1, __float2int_rd(fhi));
}

// ---------------------------------------------------------------------------
// Projector: one block = (angle chunk, z-quad). Four zero-padded fp16 slices
// in smem; each inner step produces four outputs.
// Half-warp angle split + per-j u-group rotation (R15 mapping).
// ---------------------------------------------------------------------------
__global__ __launch_bounds__(THREADS) void joseph_proj_kernel(
    const float* __restrict__ angles, float* __restrict__ out) {
    extern __shared__ h2x2 sm4[];   // [SM_ROWS][PITCH], zero border

    const int zq     = blockIdx.y;
    const int achunk = blockIdx.x;

    // zero-fill (borders), then place data at +OFS
    const h2x2 ZERO = { __half2half2(__ushort_as_half(0)), __half2half2(__ushort_as_half(0)) };
    for (int i = threadIdx.x; i < SM_ELEMS; i += THREADS) sm4[i] = ZERO;
    __syncthreads();
    const h2x2* slice = g_vol4 + zq * (NY * NX);
    for (int i = threadIdx.x; i < NY * NX; i += THREADS) {
        int y = i >> 7;
        int x = i & 127;
        sm4[(y + OFS) * PITCH + (x + OFS)] = slice[i];
    }
    __syncthreads();

    const int lane = threadIdx.x & 31;
    const int w    = threadIdx.x >> 5;       // 0..31
    const int sub  = lane & 15;
    const int hh   = lane >> 4;              // 0..1 (half-warp)
    const int wg   = w >> 2;                 // 0..7 (u-group base)
    const int slot = (w & 3) + 4 * hh;       // 0..7 (angle slot)

    const float CTR = 63.5f + (float)OFS;

#pragma unroll 1
    for (int j = 0; j < J_ITERS; ++j) {
        const int a  = achunk * A_PER_BLOCK + slot + 8 * j;
        // per-j u-group rotation (bijection per j; balances warp step totals)
        const int ug = (wg + 5 * j) & 7;
        const int u  = ug * 16 + sub;        // 0..127
        const float uu = (float)u - 63.5f;

        float s, c;
        __sincosf(angles[a], &s, &c);

        const float xA = fmaf(T0F, c, CTR - uu * s);
        const float yA = fmaf(T0F, s, CTR + uu * c);
        const float dx = DTF * c;
        const float dy = DTF * s;

        int lox, hix, loy, hiy;
        slab_range(xA, dx, (float)OFS - 1.0f, (float)OFS + 128.0f, lox, hix);
        slab_range(yA, dy, (float)OFS - 1.0f, (float)OFS + 128.0f, loy, hiy);
        const int ilo = max(lox, loy);
        const int ihi = min(hix, hiy);

        float acc0 = 0.f, acc1 = 0.f, acc2 = 0.f, acc3 = 0.f;
        float fi = (float)ilo;
#pragma unroll 8
        for (int i = ilo; i <= ihi; ++i, fi += 1.0f) {
            const float x = fmaf(fi, dx, xA);   // strictly positive
            const float y = fmaf(fi, dy, yA);

            const int ix = (int)x;              // trunc == floor (positive)
            const int iy = (int)y;
            const float fx = x - (float)ix;
            const float fy = y - (float)iy;
            const __half2 fx2 = __float2half2_rn(fx);
            const __half2 fy2 = __float2half2_rn(fy);

            const h2x2* r = sm4 + (iy * PITCH + ix);
            const h2x2 v00 = r[0];
            const h2x2 v01 = r[1];
            const h2x2 v10 = r[PITCH];
            const h2x2 v11 = r[PITCH + 1];

            // bilinear in half2 (4 z lanes), accumulate in fp32
            const __half2 m0a = __hfma2(fy2, __hsub2(v10.a, v00.a), v00.a);
            const __half2 m1a = __hfma2(fy2, __hsub2(v11.a, v01.a), v01.a);
            const __half2 m0b = __hfma2(fy2, __hsub2(v10.b, v00.b), v00.b);
            const __half2 m1b = __hfma2(fy2, __hsub2(v11.b, v01.b), v01.b);
            const __half2 ra  = __hfma2(fx2, __hsub2(m1a, m0a), m0a);
            const __half2 rb  = __hfma2(fx2, __hsub2(m1b, m0b), m0b);

            const float2 fa = __half22float2(ra);
            const float2 fb = __half22float2(rb);
            acc0 += fa.x; acc1 += fa.y; acc2 += fb.x; acc3 += fb.y;
        }

        // out shape (U, A, V): out[u][a][4zq .. 4zq+3] -> one float4 store
        float4 res = make_float4(acc0 * DTF, acc1 * DTF, acc2 * DTF, acc3 * DTF);
        *reinterpret_cast<float4*>(out + (u * NA + a) * NV + 4 * zq) = res;
    }
}

// ---------------------------------------------------------------------------
extern "C" void kernel_launch(void* const* d_in, const int* in_sizes, int n_in,
                              void* d_out, int out_size) {
    (void)in_sizes; (void)n_in; (void)out_size;
    const float* vol    = (const float*)d_in[0];
    const float* angles = (const float*)d_in[1];
    float*       out    = (float*)d_out;

    constexpr int SMEM_BYTES = SM_ELEMS * (int)sizeof(h2x2);  // 140448
    static bool attr_set = false;
    if (!attr_set) {
        cudaFuncSetAttribute(joseph_proj_kernel,
                             cudaFuncAttributeMaxDynamicSharedMemorySize, SMEM_BYTES);
        attr_set = true;
    }

    dim3 tgrid(NX / 32, NZ / 32, NY);
    dim3 tblock(32, 8);
    transpose_kernel<<<tgrid, tblock>>>(vol);

    dim3 pgrid(ACHUNKS, NZQ);
    joseph_proj_kernel<<<pgrid, THREADS, SMEM_BYTES>>>(angles, out);
}

// round 17
// speedup vs baseline: 1.6508x; 1.6508x over previous
#include <cuda_runtime.h>
#include <cuda_fp16.h>
#include <math.h>

// Problem constants (fixed shapes)
constexpr int NX = 128, NY = 128, NZ = 128;
constexpr int NA = 96, NU = 128, NV = 128, NSTEPS = 128;
constexpr int NZQ = NZ / 4;                 // 32 z-quads
constexpr int ACHUNKS = 4;                  // 96 angles / 24 per block
constexpr int A_PER_BLOCK = NA / ACHUNKS;   // 24
constexpr int THREADS = 1024;
constexpr int J_ITERS = 3;                  // 8 angle slots x 3 = 24 angles

// Zero-padded shared tile (cell = 2x half2 = 4 z-slices, 8B). Linear layout.
// EXACT clipping keeps coords in [OFS-1-eps, OFS+128+eps]; with OFS=2 all
// touched indices (incl. +1 corners) lie in [0, 131].
constexpr int OFS      = 2;
constexpr int SM_ROWS  = 132;
constexpr int PITCH    = 137;               // proven pitch (R7-R15)
constexpr int SM_ELEMS = SM_ROWS * PITCH;   // 18084 cells = 144672 B

// T = 0.5*sqrt(127^2 + 127^2), delta_t = 2T/128 (double -> f32)
constexpr float TF  = (float)89.80256121069154;
constexpr float DTF = (float)1.4031650189170553;
constexpr float T0F = -TF + 0.5f * DTF;

struct h2x2 { __half2 a, b; };   // 4 z values (z0,z1 | z2,z3)

// 4 MB scratch: vol as [z-quad][y][x], fp16, x contiguous
__device__ h2x2 g_vol4[NZQ * NY * NX];

// ---------------------------------------------------------------------------
// Transpose vol[(x*NY + y)*NZ + z] -> g_vol4[(zq*NY + y)*NX + x] (4 z packed)
// ---------------------------------------------------------------------------
__global__ void transpose_kernel(const float* __restrict__ vol) {
    __shared__ float tile[32][33];           // [x local][z local]
    const int y  = blockIdx.z;
    const int x0 = blockIdx.x * 32;
    const int z0 = blockIdx.y * 32;
    const int tx = threadIdx.x;      // 0..31
    const int ty = threadIdx.y;      // 0..7

#pragma unroll
    for (int j = 0; j < 32; j += 8) {
        int x = x0 + ty + j;
        int z = z0 + tx;
        tile[ty + j][tx] = vol[(x * NY + y) * NZ + z];   // coalesced in z
    }
    __syncthreads();
    {
        int zql = ty;                        // 0..7 (z-quad within 32-z tile)
        int x   = x0 + tx;
        int zq  = (z0 >> 2) + zql;
        h2x2 v;
        v.a = __floats2half2_rn(tile[tx][4 * zql + 0], tile[tx][4 * zql + 1]);
        v.b = __floats2half2_rn(tile[tx][4 * zql + 2], tile[tx][4 * zql + 3]);
        g_vol4[(zq * NY + y) * NX + x] = v;  // coalesced 8B
    }
}

// ---------------------------------------------------------------------------
// EXACT step range for val(i) = A + i*d in (lo_b, hi_b): lo = ceil, hi = floor.
// Steps excluded at the boundary have (near-)zero bilinear weight into the
// zero border; fp rounding of the bound (~1e-4 px) changes results by <1e-8.
// ---------------------------------------------------------------------------
__device__ __forceinline__ void slab_range(float A, float d, float lo_b, float hi_b,
                                           int& lo, int& hi) {
    if (fabsf(d) < 1e-8f) {
        if (A > lo_b && A < hi_b) { lo = 0; hi = NSTEPS - 1; }
        else                      { lo = 1; hi = 0; }
        return;
    }
    float inv = 1.0f / d;
    float i1 = (lo_b - A) * inv;
    float i2 = (hi_b - A) * inv;
    float flo = fmaxf(fminf(i1, i2), -1e9f);
    float fhi = fminf(fmaxf(i1, i2),  1e9f);
    lo = max(0, __float2int_ru(flo));
    hi = min(NSTEPS - 1, __float2int_rd(fhi));
}

// ---------------------------------------------------------------------------
// Projector: one block = (angle chunk, z-quad). Four zero-padded fp16 slices
// in smem; each inner step produces four outputs.
// Half-warp angle split + per-j u-group rotation (R15 mapping).
// ---------------------------------------------------------------------------
__global__ __launch_bounds__(THREADS) void joseph_proj_kernel(
    const float* __restrict__ angles, float* __restrict__ out) {
    extern __shared__ h2x2 sm4[];   // [SM_ROWS][PITCH], zero border

    const int zq     = blockIdx.y;
    const int achunk = blockIdx.x;

    // zero-fill (borders), then place data at +OFS
    const h2x2 ZERO = { __half2half2(__ushort_as_half(0)), __half2half2(__ushort_as_half(0)) };
    for (int i = threadIdx.x; i < SM_ELEMS; i += THREADS) sm4[i] = ZERO;
    __syncthreads();
    const h2x2* slice = g_vol4 + zq * (NY * NX);
    for (int i = threadIdx.x; i < NY * NX; i += THREADS) {
        int y = i >> 7;
        int x = i & 127;
        sm4[(y + OFS) * PITCH + (x + OFS)] = slice[i];
    }
    __syncthreads();

    const int lane = threadIdx.x & 31;
    const int w    = threadIdx.x >> 5;       // 0..31
    const int sub  = lane & 15;
    const int hh   = lane >> 4;              // 0..1 (half-warp)
    const int wg   = w >> 2;                 // 0..7 (u-group base)
    const int slot = (w & 3) + 4 * hh;       // 0..7 (angle slot)

    const float CTR = 63.5f + (float)OFS;

#pragma unroll 1
    for (int j = 0; j < J_ITERS; ++j) {
        const int a  = achunk * A_PER_BLOCK + slot + 8 * j;
        // per-j u-group rotation (bijection per j; balances warp step totals)
        const int ug = (wg + 5 * j) & 7;
        const int u  = ug * 16 + sub;        // 0..127
        const float uu = (float)u - 63.5f;

        float s, c;
        __sincosf(angles[a], &s, &c);

        const float xA = fmaf(T0F, c, CTR - uu * s);
        const float yA = fmaf(T0F, s, CTR + uu * c);
        const float dx = DTF * c;
        const float dy = DTF * s;

        int lox, hix, loy, hiy;
        slab_range(xA, dx, (float)OFS - 1.0f, (float)OFS + 128.0f, lox, hix);
        slab_range(yA, dy, (float)OFS - 1.0f, (float)OFS + 128.0f, loy, hiy);
        const int ilo = max(lox, loy);
        const int ihi = min(hix, hiy);

        float acc0 = 0.f, acc1 = 0.f, acc2 = 0.f, acc3 = 0.f;
        float fi = (float)ilo;
#pragma unroll 8
        for (int i = ilo; i <= ihi; ++i, fi += 1.0f) {
            const float x = fmaf(fi, dx, xA);   // strictly positive
            const float y = fmaf(fi, dy, yA);

            const int ix = (int)x;              // trunc == floor (positive)
            const int iy = (int)y;
            const float fx = x - (float)ix;
            const float fy = y - (float)iy;
            const __half2 fx2 = __float2half2_rn(fx);
            const __half2 fy2 = __float2half2_rn(fy);

            const h2x2* r = sm4 + (iy * PITCH + ix);
            const h2x2 v00 = r[0];
            const h2x2 v01 = r[1];
            const h2x2 v10 = r[PITCH];
            const h2x2 v11 = r[PITCH + 1];

            // bilinear in half2 (4 z lanes), accumulate in fp32
            const __half2 m0a = __hfma2(fy2, __hsub2(v10.a, v00.a), v00.a);
            const __half2 m1a = __hfma2(fy2, __hsub2(v11.a, v01.a), v01.a);
            const __half2 m0b = __hfma2(fy2, __hsub2(v10.b, v00.b), v00.b);
            const __half2 m1b = __hfma2(fy2, __hsub2(v11.b, v01.b), v01.b);
            const __half2 ra  = __hfma2(fx2, __hsub2(m1a, m0a), m0a);
            const __half2 rb  = __hfma2(fx2, __hsub2(m1b, m0b), m0b);

            const float2 fa = __half22float2(ra);
            const float2 fb = __half22float2(rb);
            acc0 += fa.x; acc1 += fa.y; acc2 += fb.x; acc3 += fb.y;
        }

        // out shape (U, A, V): out[u][a][4zq .. 4zq+3] -> one float4 store
        float4 res = make_float4(acc0 * DTF, acc1 * DTF, acc2 * DTF, acc3 * DTF);
        *reinterpret_cast<float4*>(out + (u * NA + a) * NV + 4 * zq) = res;
    }
}

// ---------------------------------------------------------------------------
extern "C" void kernel_launch(void* const* d_in, const int* in_sizes, int n_in,
                              void* d_out, int out_size) {
    (void)in_sizes; (void)n_in; (void)out_size;
    const float* vol    = (const float*)d_in[0];
    const float* angles = (const float*)d_in[1];
    float*       out    = (float*)d_out;

    constexpr int SMEM_BYTES = SM_ELEMS * (int)sizeof(h2x2);  // 144672
    static bool attr_set = false;
    if (!attr_set) {
        cudaFuncSetAttribute(joseph_proj_kernel,
                             cudaFuncAttributeMaxDynamicSharedMemorySize, SMEM_BYTES);
        attr_set = true;
    }

    dim3 tgrid(NX / 32, NZ / 32, NY);
    dim3 tblock(32, 8);
    transpose_kernel<<<tgrid, tblock>>>(vol);

    dim3 pgrid(ACHUNKS, NZQ);
    joseph_proj_kernel<<<pgrid, THREADS, SMEM_BYTES>>>(angles, out);
}